// round 16
// baseline (speedup 1.0000x reference)
#include <cuda_runtime.h>
#include <cuda_bf16.h>
#include <cuda_fp16.h>
#include <cstdint>

#define Bn 2
#define Sn 2048
#define Dn 1024
#define Hn 16
#define DKn 64

#define NELEM (4096 * 1024)
#define WELEM (1024 * 1024)

// Scratch (device globals; no allocations allowed) -- all single fp16.
__device__ __half g_xq[NELEM], g_xk[NELEM], g_xv[NELEM];
__device__ __half g_wq[WELEM], g_wk[WELEM], g_wv[WELEM], g_wo[WELEM];
__device__ __half g_Qf[NELEM];                 // [B,H,S,DK] pre-scaled
__device__ __half g_Kf[NELEM];
__device__ __half g_Vf[NELEM];
__device__ __half g_Af[NELEM];                 // attn out [B,S,D]

// ---------------------------------------------------------------------------
// Helpers
// ---------------------------------------------------------------------------
__device__ __forceinline__ uint32_t smem_u32(const void* p) {
    uint32_t a;
    asm("{ .reg .u64 t; cvta.to.shared.u64 t, %1; cvt.u32.u64 %0, t; }"
        : "=r"(a) : "l"(p));
    return a;
}

__device__ __forceinline__ void ldsm_x4(uint32_t (&r)[4], uint32_t addr) {
    asm volatile("ldmatrix.sync.aligned.m8n8.x4.shared.b16 {%0,%1,%2,%3}, [%4];"
        : "=r"(r[0]), "=r"(r[1]), "=r"(r[2]), "=r"(r[3]) : "r"(addr));
}

__device__ __forceinline__ void ldsm_x4_t(uint32_t (&r)[4], uint32_t addr) {
    asm volatile("ldmatrix.sync.aligned.m8n8.x4.trans.shared.b16 {%0,%1,%2,%3}, [%4];"
        : "=r"(r[0]), "=r"(r[1]), "=r"(r[2]), "=r"(r[3]) : "r"(addr));
}

// fp16 MMA
__device__ __forceinline__ void mma16816h(float (&d)[4], const uint32_t (&a)[4],
                                          uint32_t b0, uint32_t b1) {
    asm volatile(
        "mma.sync.aligned.m16n8k16.row.col.f32.f16.f16.f32 "
        "{%0,%1,%2,%3}, {%4,%5,%6,%7}, {%8,%9}, {%0,%1,%2,%3};"
        : "+f"(d[0]), "+f"(d[1]), "+f"(d[2]), "+f"(d[3])
        : "r"(a[0]), "r"(a[1]), "r"(a[2]), "r"(a[3]), "r"(b0), "r"(b1));
}

#define CP_ASYNC16(dst, src) \
    asm volatile("cp.async.cg.shared.global [%0], [%1], 16;" \
                 :: "r"(dst), "l"(src) : "memory")
#define CP_COMMIT()  asm volatile("cp.async.commit_group;" ::: "memory")
#define CP_WAIT0()   asm volatile("cp.async.wait_group 0;" ::: "memory")
#define CP_WAIT1()   asm volatile("cp.async.wait_group 1;" ::: "memory")

// fp16 pack (single) of a float4
__device__ __forceinline__ uint2 pack4h(float4 v) {
    uint2 o;
    o.x = ((uint32_t)__half_as_ushort(__float2half_rn(v.y)) << 16) |
          __half_as_ushort(__float2half_rn(v.x));
    o.y = ((uint32_t)__half_as_ushort(__float2half_rn(v.w)) << 16) |
          __half_as_ushort(__float2half_rn(v.z));
    return o;
}

__device__ __forceinline__ uint32_t packh2(float a, float b) {
    return ((uint32_t)__half_as_ushort(__float2half_rn(b)) << 16) |
           __half_as_ushort(__float2half_rn(a));
}

// Fast 2^x on the FMA pipe. Valid for x <= 0 (clamped at -126). |err|~2.4e-6.
__device__ __forceinline__ float fexp2(float x) {
    x = fmaxf(x, -126.0f);
    float n = rintf(x);
    float r = x - n;
    float p = fmaf(r, 1.3333558e-3f, 9.6181291e-3f);
    p = fmaf(r, p, 5.5504109e-2f);
    p = fmaf(r, p, 2.4022651e-1f);
    p = fmaf(r, p, 6.9314718e-1f);
    p = fmaf(r, p, 1.0f);
    int e = ((int)n + 127) << 23;
    return p * __int_as_float(e);
}

// ---------------------------------------------------------------------------
// Prepass: all 7 tensors -> single fp16. One launch.
// ---------------------------------------------------------------------------
__global__ __launch_bounds__(256) void conv_all(
    const float* __restrict__ q, const float* __restrict__ k,
    const float* __restrict__ v,
    const float* __restrict__ wq, const float* __restrict__ wk,
    const float* __restrict__ wv, const float* __restrict__ wo,
    __half* xq, __half* xk, __half* xv,
    __half* dwq, __half* dwk, __half* dwv, __half* dwo)
{
    const int z = blockIdx.y;
    const float* src;
    __half* H;
    int n4;
    switch (z) {
        case 0: src = q;  H = xq;  n4 = NELEM / 4; break;
        case 1: src = k;  H = xk;  n4 = NELEM / 4; break;
        case 2: src = v;  H = xv;  n4 = NELEM / 4; break;
        case 3: src = wq; H = dwq; n4 = WELEM / 4; break;
        case 4: src = wk; H = dwk; n4 = WELEM / 4; break;
        case 5: src = wv; H = dwv; n4 = WELEM / 4; break;
        default: src = wo; H = dwo; n4 = WELEM / 4; break;
    }
    const int base = blockIdx.x * 1024 + threadIdx.x;
    if (base >= n4) return;
#pragma unroll
    for (int u = 0; u < 4; u++) {
        const int i = base + u * 256;
        if (i < n4)
            ((uint2*)H)[i] = pack4h(((const float4*)src)[i]);
    }
}

// ---------------------------------------------------------------------------
// fp16 HMMA GEMM body, single-term (X*W), BK=64 per stage, cp.async 2-stage,
// 2 CTAs/SM. 16 mainloop iterations (halved barrier cadence).
// MODE 1: single fp16 out permuted [B,H,S,DK]. MODE 0: fp32 row-major out.
// ---------------------------------------------------------------------------
#define LDA_S   144                      // 128B data + 16B pad (ldsm-safe)
#define MAT_SZ  (128 * LDA_S)            // 18432
#define STG_SZ  (2 * MAT_SZ)             // 36864: X, W
#define GEMM_SMEM (2 * STG_SZ)           // 73728

struct GemmJob {
    const __half *X, *W;
    const float* bias;
    __half *Y;
    float oscale;
};

template <int MODE>
__device__ __forceinline__ void gemm_body(
    const __half* __restrict__ X,
    const __half* __restrict__ W,
    const float* __restrict__ bias,
    float* __restrict__ Yf,
    __half* __restrict__ Yh,
    float oscale, char* sm)
{
    const uint32_t sb = smem_u32(sm);
    const int tid  = threadIdx.x;
    const int lane = tid & 31;
    const int wid  = tid >> 5;
    const int wm   = wid >> 1;
    const int wn   = wid & 1;

    const int m0 = blockIdx.x * 128;
    const int n0 = blockIdx.y * 128;
    const __half* src[2] = { X + (size_t)m0 * Dn, W + (size_t)n0 * Dn };

    // loader: 128 rows x 8 chunks(16B) per matrix; 4 rows per thread
    const int lr = tid >> 3;             // 0..31
    const int lc = (tid & 7) * 16;       // byte offset in 128B row
    const int le = lc >> 1;              // fp16 element offset

    const uint32_t a_row = wm * 32 + (lane & 15);
    const uint32_t a_byt = (lane >> 4) * 16;
    const uint32_t b_row = wn * 64 + (lane & 7) + ((lane >> 4) << 3);
    const uint32_t b_byt = ((lane >> 3) & 1) * 16;

    float acc[2][8][4];
#pragma unroll
    for (int i = 0; i < 2; i++)
#pragma unroll
        for (int j = 0; j < 8; j++)
#pragma unroll
            for (int k = 0; k < 4; k++) acc[i][j][k] = 0.f;

    // prologue: stages 0,1 (k = 0..63, 64..127)
#pragma unroll
    for (int ps = 0; ps < 2; ps++) {
        const uint32_t st = sb + ps * STG_SZ;
#pragma unroll
        for (int mt = 0; mt < 2; mt++)
#pragma unroll
            for (int rr = 0; rr < 4; rr++) {
                const int row = lr + rr * 32;
                CP_ASYNC16(st + mt * MAT_SZ + row * LDA_S + lc,
                           src[mt] + (size_t)row * Dn + ps * 64 + le);
            }
        CP_COMMIT();
    }

#pragma unroll 1
    for (int s = 0; s < 16; s++) {
        CP_WAIT1();
        __syncthreads();

        const uint32_t stg = sb + (s & 1) * STG_SZ;
#pragma unroll
        for (int ks = 0; ks < 4; ks++) {
            uint32_t ah[2][4], bh[4][4];
#pragma unroll
            for (int mf = 0; mf < 2; mf++) {
                const uint32_t ao = stg + (a_row + mf * 16) * LDA_S + ks * 32 + a_byt;
                ldsm_x4(ah[mf], ao);
            }
#pragma unroll
            for (int nq = 0; nq < 4; nq++) {
                const uint32_t bo = stg + MAT_SZ +
                                    (b_row + nq * 16) * LDA_S + ks * 32 + b_byt;
                ldsm_x4(bh[nq], bo);
            }
#pragma unroll
            for (int nq = 0; nq < 4; nq++)
#pragma unroll
                for (int mf = 0; mf < 2; mf++) {
                    mma16816h(acc[mf][nq * 2 + 0], ah[mf], bh[nq][0], bh[nq][1]);
                    mma16816h(acc[mf][nq * 2 + 1], ah[mf], bh[nq][2], bh[nq][3]);
                }
        }

        __syncthreads();
        if (s + 2 < 16) {
            const uint32_t st = sb + (s & 1) * STG_SZ;   // reuse just-freed buf
            const int k8 = (s + 2) * 64 + le;
#pragma unroll
            for (int mt = 0; mt < 2; mt++)
#pragma unroll
                for (int rr = 0; rr < 4; rr++) {
                    const int row = lr + rr * 32;
                    CP_ASYNC16(st + mt * MAT_SZ + row * LDA_S + lc,
                               src[mt] + (size_t)row * Dn + k8);
                }
        }
        CP_COMMIT();
    }

#pragma unroll
    for (int mf = 0; mf < 2; mf++) {
        const int mr = m0 + wm * 32 + mf * 16 + (lane >> 2);
#pragma unroll
        for (int nf = 0; nf < 8; nf++) {
            const int c0 = n0 + wn * 64 + nf * 8 + (lane & 3) * 2;
            const float b0 = bias[c0], b1 = bias[c0 + 1];
#pragma unroll
            for (int rr = 0; rr < 2; rr++) {
                const int m = mr + rr * 8;
                float v0 = acc[mf][nf][rr * 2 + 0] + b0;
                float v1 = acc[mf][nf][rr * 2 + 1] + b1;
                if (MODE) {
                    v0 *= oscale; v1 *= oscale;
                    const int b = m >> 11, srow = m & (Sn - 1);
                    const int h = c0 >> 6, dk = c0 & 63;
                    const size_t idx =
                        (((size_t)(b * Hn + h)) * Sn + srow) * DKn + dk;
                    *(uint32_t*)(Yh + idx) = packh2(v0, v1);
                } else {
                    float* dst = Yf + (size_t)m * Dn + c0;
                    dst[0] = v0; dst[1] = v1;
                }
            }
        }
    }
}

__global__ __launch_bounds__(256, 2) void gemm_proj(GemmJob a, GemmJob b, GemmJob c)
{
    extern __shared__ char sm[];
    GemmJob j = (blockIdx.z == 0) ? a : ((blockIdx.z == 1) ? b : c);
    gemm_body<1>(j.X, j.W, j.bias, nullptr, j.Y, j.oscale, sm);
}

__global__ __launch_bounds__(256, 2) void gemm_out(
    const __half* X, const __half* W, const float* bias, float* Yf)
{
    extern __shared__ char sm[];
    gemm_body<0>(X, W, bias, Yf, nullptr, 1.0f, sm);
}

// ---------------------------------------------------------------------------
// fp16 HMMA causal flash attention, single-precision Q, K, V (unchanged).
// ---------------------------------------------------------------------------
#define LDS_B   144
#define QMAT    18432                  // 128 * 144 (single Q)
#define KVMAT   9216                   // 64 * 144
#define KV_STG  (2 * KVMAT)            // 18432: Kf, Vf
#define ATTN_SMEM (2 * KV_STG)         // 36864 (Q staged in buf1 then reused)

__global__ __launch_bounds__(256, 2) void attn_tc()
{
    extern __shared__ char smem[];
    const uint32_t sb = smem_u32(smem);
    const int tid = threadIdx.x, lane = tid & 31, wid = tid >> 5;

    const int qt = 15 - blockIdx.x;       // heavy blocks first
    const int bh = blockIdx.y;
    const int q0 = qt * 128;

    const size_t base = (size_t)bh * Sn * DKn;
    const __half* Qf = g_Qf + base;
    const __half* Kf = g_Kf + base;
    const __half* Vf = g_Vf + base;

    // ---- stage Q (single fp16) into buf1, pull into A-frags ----
    {
        char* qd = smem + KV_STG;
#pragma unroll
        for (int i = 0; i < 4; i++) {
            const int c = tid + i * 256;        // 1024 chunks of 16B
            const int row = c >> 3, ch = c & 7;
            *(uint4*)(qd + row * LDS_B + ch * 16) =
                *(const uint4*)(Qf + (size_t)(q0 + row) * DKn + ch * 8);
        }
    }
    __syncthreads();

    uint32_t qf[4][4];
    {
        const uint32_t arow = wid * 16 + (lane & 15);
        const uint32_t abyt = (lane >> 4) * 16;
#pragma unroll
        for (int kc = 0; kc < 4; kc++)
            ldsm_x4(qf[kc], sb + KV_STG + arow * LDS_B + kc * 32 + abyt);
    }

    float accO[8][4];
#pragma unroll
    for (int j = 0; j < 8; j++)
#pragma unroll
        for (int k = 0; k < 4; k++) accO[j][k] = 0.f;
    float m_lo = -1e30f, m_hi = -1e30f, l_lo = 0.f, l_hi = 0.f;

    const int r_lo = q0 + wid * 16 + (lane >> 2);
    const int r_hi = r_lo + 8;
    const uint32_t brow = (lane & 7) + ((lane >> 4) << 3);
    const uint32_t bbyt = ((lane >> 3) & 1) * 16;
    const uint32_t vbyt = (lane >> 4) * 16;

    const int ntiles = 2 * qt + 2;

    const int lr = tid >> 3;              // 0..31
    const int lc = (tid & 7) * 16;
    const int le = lc >> 1;

    {
        const uint32_t st = sb;
#pragma unroll
        for (int rr = 0; rr < 2; rr++) {
            const int row = lr + rr * 32;
            const uint32_t so = row * LDS_B + lc;
            const size_t go = (size_t)row * DKn + le;
            CP_ASYNC16(st + 0 * KVMAT + so, Kf + go);
            CP_ASYNC16(st + 1 * KVMAT + so, Vf + go);
        }
        CP_COMMIT();
    }

#pragma unroll 1
    for (int kt = 0; kt < ntiles; kt++) {
        CP_WAIT0();
        __syncthreads();

        if (kt + 1 < ntiles) {
            const uint32_t st = sb + ((kt + 1) & 1) * KV_STG;
#pragma unroll
            for (int rr = 0; rr < 2; rr++) {
                const int row = lr + rr * 32;
                const uint32_t so = row * LDS_B + lc;
                const size_t go = (size_t)((kt + 1) * 64 + row) * DKn + le;
                CP_ASYNC16(st + 0 * KVMAT + so, Kf + go);
                CP_ASYNC16(st + 1 * KVMAT + so, Vf + go);
            }
        }
        CP_COMMIT();

        const uint32_t stg = sb + (kt & 1) * KV_STG;
        const int k0 = kt * 64;

        // ---- S = Q K^T, log2-domain scores ----
        float s[8][4];
#pragma unroll
        for (int j = 0; j < 8; j++)
#pragma unroll
            for (int k = 0; k < 4; k++) s[j][k] = 0.f;

#pragma unroll
        for (int kc = 0; kc < 4; kc++) {
#pragma unroll
            for (int nq = 0; nq < 4; nq++) {
                const uint32_t bo = stg + (brow + nq * 16) * LDS_B + kc * 32 + bbyt;
                uint32_t kh[4];
                ldsm_x4(kh, bo);
                mma16816h(s[nq * 2 + 0], qf[kc], kh[0], kh[1]);
                mma16816h(s[nq * 2 + 1], qf[kc], kh[2], kh[3]);
            }
        }

        // ---- causal mask ----
        if ((k0 + 63) > r_lo) {
#pragma unroll
            for (int j = 0; j < 8; j++) {
                const int c = k0 + j * 8 + (lane & 3) * 2;
                if (c > r_lo)     s[j][0] = -1e30f;
                if (c + 1 > r_lo) s[j][1] = -1e30f;
                if (c > r_hi)     s[j][2] = -1e30f;
                if (c + 1 > r_hi) s[j][3] = -1e30f;
            }
        }

        // ---- online softmax (base-2) ----
        float mx0 = -1e30f, mx1 = -1e30f;
#pragma unroll
        for (int j = 0; j < 8; j++) {
            mx0 = fmaxf(mx0, fmaxf(s[j][0], s[j][1]));
            mx1 = fmaxf(mx1, fmaxf(s[j][2], s[j][3]));
        }
        mx0 = fmaxf(mx0, __shfl_xor_sync(0xffffffffu, mx0, 1));
        mx0 = fmaxf(mx0, __shfl_xor_sync(0xffffffffu, mx0, 2));
        mx1 = fmaxf(mx1, __shfl_xor_sync(0xffffffffu, mx1, 1));
        mx1 = fmaxf(mx1, __shfl_xor_sync(0xffffffffu, mx1, 2));
        const float mn0 = fmaxf(m_lo, mx0);
        const float mn1 = fmaxf(m_hi, mx1);
        const float a0 = fexp2(m_lo - mn0);
        const float a1 = fexp2(m_hi - mn1);
        m_lo = mn0; m_hi = mn1;

        float sum0 = 0.f, sum1 = 0.f;
#pragma unroll
        for (int j = 0; j < 8; j++) {
            s[j][0] = fexp2(s[j][0] - mn0);
            s[j][1] = fexp2(s[j][1] - mn0);
            s[j][2] = fexp2(s[j][2] - mn1);
            s[j][3] = fexp2(s[j][3] - mn1);
            sum0 += s[j][0] + s[j][1];
            sum1 += s[j][2] + s[j][3];
        }
        sum0 += __shfl_xor_sync(0xffffffffu, sum0, 1);
        sum0 += __shfl_xor_sync(0xffffffffu, sum0, 2);
        sum1 += __shfl_xor_sync(0xffffffffu, sum1, 1);
        sum1 += __shfl_xor_sync(0xffffffffu, sum1, 2);
        l_lo = l_lo * a0 + sum0;
        l_hi = l_hi * a1 + sum1;
#pragma unroll
        for (int j = 0; j < 8; j++) {
            accO[j][0] *= a0; accO[j][1] *= a0;
            accO[j][2] *= a1; accO[j][3] *= a1;
        }

        // ---- O += P V ----
#pragma unroll
        for (int kc = 0; kc < 4; kc++) {
            uint32_t ph[4];
            ph[0] = packh2(s[2 * kc][0],     s[2 * kc][1]);
            ph[1] = packh2(s[2 * kc][2],     s[2 * kc][3]);
            ph[2] = packh2(s[2 * kc + 1][0], s[2 * kc + 1][1]);
            ph[3] = packh2(s[2 * kc + 1][2], s[2 * kc + 1][3]);
            const uint32_t vrow = kc * 16 + (lane & 15);
#pragma unroll
            for (int np = 0; np < 4; np++) {
                const uint32_t vo = stg + KVMAT + vrow * LDS_B + np * 32 + vbyt;
                uint32_t vh[4];
                ldsm_x4_t(vh, vo);
                mma16816h(accO[np * 2 + 0], ph, vh[0], vh[1]);
                mma16816h(accO[np * 2 + 1], ph, vh[2], vh[3]);
            }
        }
    }

    // ---- epilogue: normalize, write single fp16 [B,S,D] ----
    const float il0 = 1.0f / l_lo;
    const float il1 = 1.0f / l_hi;
    const int b = bh >> 4, h = bh & 15;
    const int c_base = h * DKn + (lane & 3) * 2;
#pragma unroll
    for (int j = 0; j < 8; j++) {
        const int c = c_base + j * 8;
        const size_t i0 = ((size_t)(b * Sn + r_lo)) * Dn + c;
        const size_t i1 = ((size_t)(b * Sn + r_hi)) * Dn + c;
        *(uint32_t*)(g_Af + i0) = packh2(accO[j][0] * il0, accO[j][1] * il0);
        *(uint32_t*)(g_Af + i1) = packh2(accO[j][2] * il1, accO[j][3] * il1);
    }
}

// ---------------------------------------------------------------------------
extern "C" void kernel_launch(void* const* d_in, const int* in_sizes, int n_in,
                              void* d_out, int out_size)
{
    const float* k_in = (const float*)d_in[0];
    const float* q_in = (const float*)d_in[1];
    const float* v_in = (const float*)d_in[2];
    const float* w_q  = (const float*)d_in[3];
    const float* b_q  = (const float*)d_in[4];
    const float* w_k  = (const float*)d_in[5];
    const float* b_k  = (const float*)d_in[6];
    const float* w_v  = (const float*)d_in[7];
    const float* b_v  = (const float*)d_in[8];
    const float* w_o  = (const float*)d_in[9];
    const float* b_o  = (const float*)d_in[10];
    float* out = (float*)d_out;

    __half *xq, *xk, *xv, *wq, *wk, *wv, *wo;
    __half *Qf, *Kf, *Vf, *Af;
    cudaGetSymbolAddress((void**)&xq, g_xq);
    cudaGetSymbolAddress((void**)&xk, g_xk);
    cudaGetSymbolAddress((void**)&xv, g_xv);
    cudaGetSymbolAddress((void**)&wq, g_wq);
    cudaGetSymbolAddress((void**)&wk, g_wk);
    cudaGetSymbolAddress((void**)&wv, g_wv);
    cudaGetSymbolAddress((void**)&wo, g_wo);
    cudaGetSymbolAddress((void**)&Qf, g_Qf);
    cudaGetSymbolAddress((void**)&Kf, g_Kf);
    cudaGetSymbolAddress((void**)&Vf, g_Vf);
    cudaGetSymbolAddress((void**)&Af, g_Af);

    cudaFuncSetAttribute(gemm_proj, cudaFuncAttributeMaxDynamicSharedMemorySize,
                         GEMM_SMEM);
    cudaFuncSetAttribute(gemm_out, cudaFuncAttributeMaxDynamicSharedMemorySize,
                         GEMM_SMEM);
    cudaFuncSetAttribute(attn_tc, cudaFuncAttributeMaxDynamicSharedMemorySize,
                         ATTN_SMEM);

    // one-launch conversion prepass
    conv_all<<<dim3(1024, 7), 256>>>(
        q_in, k_in, v_in, w_q, w_k, w_v, w_o,
        xq, xk, xv, wq, wk, wv, wo);

    // merged Q/K/V projection GEMMs (single fp16; Q pre-scaled into log2 domain)
    GemmJob jq = { xq, wq, b_q, Qf, 0.125f * 1.4426950408889634f };
    GemmJob jk = { xk, wk, b_k, Kf, 1.0f };
    GemmJob jv = { xv, wv, b_v, Vf, 1.0f };
    gemm_proj<<<dim3(32, 8, 3), 256, GEMM_SMEM>>>(jq, jk, jv);

    attn_tc<<<dim3(16, 32), 256, ATTN_SMEM>>>();

    gemm_out<<<dim3(32, 8), 256, GEMM_SMEM>>>(Af, wo, b_o, out);
}

// round 17
// speedup vs baseline: 1.4442x; 1.4442x over previous
#include <cuda_runtime.h>
#include <cuda_bf16.h>
#include <cuda_fp16.h>
#include <cstdint>

#define Bn 2
#define Sn 2048
#define Dn 1024
#define Hn 16
#define DKn 64

#define NELEM (4096 * 1024)
#define WELEM (1024 * 1024)

// Scratch (device globals; no allocations allowed) -- all single fp16.
__device__ __half g_xq[NELEM], g_xk[NELEM], g_xv[NELEM];
__device__ __half g_wq[WELEM], g_wk[WELEM], g_wv[WELEM], g_wo[WELEM];
__device__ __half g_Qf[NELEM];                 // [B,H,S,DK] pre-scaled
__device__ __half g_Kf[NELEM];
__device__ __half g_Vf[NELEM];
__device__ __half g_Af[NELEM];                 // attn out [B,S,D]

// ---------------------------------------------------------------------------
// Helpers
// ---------------------------------------------------------------------------
__device__ __forceinline__ uint32_t smem_u32(const void* p) {
    uint32_t a;
    asm("{ .reg .u64 t; cvta.to.shared.u64 t, %1; cvt.u32.u64 %0, t; }"
        : "=r"(a) : "l"(p));
    return a;
}

__device__ __forceinline__ void ldsm_x4(uint32_t (&r)[4], uint32_t addr) {
    asm volatile("ldmatrix.sync.aligned.m8n8.x4.shared.b16 {%0,%1,%2,%3}, [%4];"
        : "=r"(r[0]), "=r"(r[1]), "=r"(r[2]), "=r"(r[3]) : "r"(addr));
}

__device__ __forceinline__ void ldsm_x4_t(uint32_t (&r)[4], uint32_t addr) {
    asm volatile("ldmatrix.sync.aligned.m8n8.x4.trans.shared.b16 {%0,%1,%2,%3}, [%4];"
        : "=r"(r[0]), "=r"(r[1]), "=r"(r[2]), "=r"(r[3]) : "r"(addr));
}

// fp16 MMA
__device__ __forceinline__ void mma16816h(float (&d)[4], const uint32_t (&a)[4],
                                          uint32_t b0, uint32_t b1) {
    asm volatile(
        "mma.sync.aligned.m16n8k16.row.col.f32.f16.f16.f32 "
        "{%0,%1,%2,%3}, {%4,%5,%6,%7}, {%8,%9}, {%0,%1,%2,%3};"
        : "+f"(d[0]), "+f"(d[1]), "+f"(d[2]), "+f"(d[3])
        : "r"(a[0]), "r"(a[1]), "r"(a[2]), "r"(a[3]), "r"(b0), "r"(b1));
}

#define CP_ASYNC16(dst, src) \
    asm volatile("cp.async.cg.shared.global [%0], [%1], 16;" \
                 :: "r"(dst), "l"(src) : "memory")
#define CP_COMMIT()  asm volatile("cp.async.commit_group;" ::: "memory")
#define CP_WAIT0()   asm volatile("cp.async.wait_group 0;" ::: "memory")
#define CP_WAIT1()   asm volatile("cp.async.wait_group 1;" ::: "memory")

// fp16 pack (single) of a float4
__device__ __forceinline__ uint2 pack4h(float4 v) {
    uint2 o;
    o.x = ((uint32_t)__half_as_ushort(__float2half_rn(v.y)) << 16) |
          __half_as_ushort(__float2half_rn(v.x));
    o.y = ((uint32_t)__half_as_ushort(__float2half_rn(v.w)) << 16) |
          __half_as_ushort(__float2half_rn(v.z));
    return o;
}

__device__ __forceinline__ uint32_t packh2(float a, float b) {
    return ((uint32_t)__half_as_ushort(__float2half_rn(b)) << 16) |
           __half_as_ushort(__float2half_rn(a));
}

// Fast 2^x on the FMA pipe. Valid for x <= 0 (clamped at -126). |err|~2.4e-6.
__device__ __forceinline__ float fexp2(float x) {
    x = fmaxf(x, -126.0f);
    float n = rintf(x);
    float r = x - n;
    float p = fmaf(r, 1.3333558e-3f, 9.6181291e-3f);
    p = fmaf(r, p, 5.5504109e-2f);
    p = fmaf(r, p, 2.4022651e-1f);
    p = fmaf(r, p, 6.9314718e-1f);
    p = fmaf(r, p, 1.0f);
    int e = ((int)n + 127) << 23;
    return p * __int_as_float(e);
}

// ---------------------------------------------------------------------------
// Prepass: all 7 tensors -> single fp16. One launch.
// ---------------------------------------------------------------------------
__global__ __launch_bounds__(256) void conv_all(
    const float* __restrict__ q, const float* __restrict__ k,
    const float* __restrict__ v,
    const float* __restrict__ wq, const float* __restrict__ wk,
    const float* __restrict__ wv, const float* __restrict__ wo,
    __half* xq, __half* xk, __half* xv,
    __half* dwq, __half* dwk, __half* dwv, __half* dwo)
{
    const int z = blockIdx.y;
    const float* src;
    __half* H;
    int n4;
    switch (z) {
        case 0: src = q;  H = xq;  n4 = NELEM / 4; break;
        case 1: src = k;  H = xk;  n4 = NELEM / 4; break;
        case 2: src = v;  H = xv;  n4 = NELEM / 4; break;
        case 3: src = wq; H = dwq; n4 = WELEM / 4; break;
        case 4: src = wk; H = dwk; n4 = WELEM / 4; break;
        case 5: src = wv; H = dwv; n4 = WELEM / 4; break;
        default: src = wo; H = dwo; n4 = WELEM / 4; break;
    }
    const int base = blockIdx.x * 1024 + threadIdx.x;
    if (base >= n4) return;
#pragma unroll
    for (int u = 0; u < 4; u++) {
        const int i = base + u * 256;
        if (i < n4)
            ((uint2*)H)[i] = pack4h(((const float4*)src)[i]);
    }
}

// ---------------------------------------------------------------------------
// fp16 HMMA GEMM body, single-term (X*W), BK=32, cp.async 3-stage pipeline,
// ONE barrier per iteration, 2 CTAs/SM.
// MODE 1: single fp16 out permuted [B,H,S,DK]. MODE 0: fp32 row-major out.
// ---------------------------------------------------------------------------
#define LDA_S   80
#define MAT_SZ  (128 * LDA_S)            // 10240
#define STG_SZ  (2 * MAT_SZ)             // 20480: X, W
#define GEMM_SMEM (3 * STG_SZ)           // 61440

struct GemmJob {
    const __half *X, *W;
    const float* bias;
    __half *Y;
    float oscale;
};

template <int MODE>
__device__ __forceinline__ void gemm_body(
    const __half* __restrict__ X,
    const __half* __restrict__ W,
    const float* __restrict__ bias,
    float* __restrict__ Yf,
    __half* __restrict__ Yh,
    float oscale, char* sm)
{
    const uint32_t sb = smem_u32(sm);
    const int tid  = threadIdx.x;
    const int lane = tid & 31;
    const int wid  = tid >> 5;
    const int wm   = wid >> 1;
    const int wn   = wid & 1;

    const int m0 = blockIdx.x * 128;
    const int n0 = blockIdx.y * 128;
    const __half* src[2] = { X + (size_t)m0 * Dn, W + (size_t)n0 * Dn };

    const int cr0 = (tid + 0)   >> 2;     // rows 0..63
    const int cc0 = (tid & 3)   * 16;     // 16B chunk in 64B row-slab
    const int cr1 = (tid + 256) >> 2;     // rows 64..127

    const uint32_t a_row = wm * 32 + (lane & 15);
    const uint32_t a_byt = (lane >> 4) * 16;
    const uint32_t b_row = wn * 64 + (lane & 7) + ((lane >> 4) << 3);
    const uint32_t b_byt = ((lane >> 3) & 1) * 16;

    float acc[2][8][4];
#pragma unroll
    for (int i = 0; i < 2; i++)
#pragma unroll
        for (int j = 0; j < 8; j++)
#pragma unroll
            for (int k = 0; k < 4; k++) acc[i][j][k] = 0.f;

    // prologue: stages 0,1
#pragma unroll
    for (int ps = 0; ps < 2; ps++) {
        const uint32_t st = sb + ps * STG_SZ;
#pragma unroll
        for (int mt = 0; mt < 2; mt++) {
            CP_ASYNC16(st + mt * MAT_SZ + cr0 * LDA_S + cc0,
                       src[mt] + (size_t)cr0 * Dn + ps * 32 + (cc0 >> 1));
            CP_ASYNC16(st + mt * MAT_SZ + cr1 * LDA_S + cc0,
                       src[mt] + (size_t)cr1 * Dn + ps * 32 + (cc0 >> 1));
        }
        CP_COMMIT();
    }

#pragma unroll 1
    for (int s = 0; s < 32; s++) {
        CP_WAIT1();               // stage s resident (s+1 still in flight)
        __syncthreads();          // all threads' groups drained + buffer free

        // prefetch s+2 into (s+2)%3 == (s-1)%3 (consumed before the barrier)
        if (s + 2 < 32) {
            const uint32_t st = sb + ((s + 2) % 3) * STG_SZ;
            const int k8 = (s + 2) * 32 + (cc0 >> 1);
#pragma unroll
            for (int mt = 0; mt < 2; mt++) {
                CP_ASYNC16(st + mt * MAT_SZ + cr0 * LDA_S + cc0,
                           src[mt] + (size_t)cr0 * Dn + k8);
                CP_ASYNC16(st + mt * MAT_SZ + cr1 * LDA_S + cc0,
                           src[mt] + (size_t)cr1 * Dn + k8);
            }
        }
        CP_COMMIT();

        const uint32_t stg = sb + (s % 3) * STG_SZ;
#pragma unroll
        for (int ks = 0; ks < 2; ks++) {
            uint32_t ah[2][4], bh[4][4];
#pragma unroll
            for (int mf = 0; mf < 2; mf++) {
                const uint32_t ao = stg + (a_row + mf * 16) * LDA_S + ks * 32 + a_byt;
                ldsm_x4(ah[mf], ao);
            }
#pragma unroll
            for (int nq = 0; nq < 4; nq++) {
                const uint32_t bo = stg + MAT_SZ +
                                    (b_row + nq * 16) * LDA_S + ks * 32 + b_byt;
                ldsm_x4(bh[nq], bo);
            }
#pragma unroll
            for (int nq = 0; nq < 4; nq++)
#pragma unroll
                for (int mf = 0; mf < 2; mf++) {
                    mma16816h(acc[mf][nq * 2 + 0], ah[mf], bh[nq][0], bh[nq][1]);
                    mma16816h(acc[mf][nq * 2 + 1], ah[mf], bh[nq][2], bh[nq][3]);
                }
        }
    }

#pragma unroll
    for (int mf = 0; mf < 2; mf++) {
        const int mr = m0 + wm * 32 + mf * 16 + (lane >> 2);
#pragma unroll
        for (int nf = 0; nf < 8; nf++) {
            const int c0 = n0 + wn * 64 + nf * 8 + (lane & 3) * 2;
            const float b0 = bias[c0], b1 = bias[c0 + 1];
#pragma unroll
            for (int rr = 0; rr < 2; rr++) {
                const int m = mr + rr * 8;
                float v0 = acc[mf][nf][rr * 2 + 0] + b0;
                float v1 = acc[mf][nf][rr * 2 + 1] + b1;
                if (MODE) {
                    v0 *= oscale; v1 *= oscale;
                    const int b = m >> 11, srow = m & (Sn - 1);
                    const int h = c0 >> 6, dk = c0 & 63;
                    const size_t idx =
                        (((size_t)(b * Hn + h)) * Sn + srow) * DKn + dk;
                    *(uint32_t*)(Yh + idx) = packh2(v0, v1);
                } else {
                    float* dst = Yf + (size_t)m * Dn + c0;
                    dst[0] = v0; dst[1] = v1;
                }
            }
        }
    }
}

__global__ __launch_bounds__(256, 2) void gemm_proj(GemmJob a, GemmJob b, GemmJob c)
{
    extern __shared__ char sm[];
    GemmJob j = (blockIdx.z == 0) ? a : ((blockIdx.z == 1) ? b : c);
    gemm_body<1>(j.X, j.W, j.bias, nullptr, j.Y, j.oscale, sm);
}

__global__ __launch_bounds__(256, 2) void gemm_out(
    const __half* X, const __half* W, const float* bias, float* Yf)
{
    extern __shared__ char sm[];
    gemm_body<0>(X, W, bias, Yf, nullptr, 1.0f, sm);
}

// ---------------------------------------------------------------------------
// fp16 HMMA causal flash attention, single-precision Q, K, V.
// 3-stage KV ring (CP_WAIT1: ~2 tiles of load slack), 2 CTAs/SM.
// Scores in log2 domain (Q pre-scaled by 0.125*log2e), fexp2 softmax.
// ---------------------------------------------------------------------------
#define LDS_B   144
#define KVMAT   9216                   // 64 * 144
#define KV_STG  (2 * KVMAT)            // 18432: Kf, Vf per stage
#define ATTN_SMEM (3 * KV_STG)         // 55296 (Q staged in stage-1 region)

__global__ __launch_bounds__(256, 2) void attn_tc()
{
    extern __shared__ char smem[];
    const uint32_t sb = smem_u32(smem);
    const int tid = threadIdx.x, lane = tid & 31, wid = tid >> 5;

    const int qt = 15 - blockIdx.x;       // heavy blocks first
    const int bh = blockIdx.y;
    const int q0 = qt * 128;

    const size_t base = (size_t)bh * Sn * DKn;
    const __half* Qf = g_Qf + base;
    const __half* Kf = g_Kf + base;
    const __half* Vf = g_Vf + base;

    // ---- stage Q (single fp16) into stage-1 region, pull into A-frags ----
    {
        char* qd = smem + KV_STG;
#pragma unroll
        for (int i = 0; i < 4; i++) {
            const int c = tid + i * 256;        // 1024 chunks of 16B
            const int row = c >> 3, ch = c & 7;
            *(uint4*)(qd + row * LDS_B + ch * 16) =
                *(const uint4*)(Qf + (size_t)(q0 + row) * DKn + ch * 8);
        }
    }
    __syncthreads();

    uint32_t qf[4][4];
    {
        const uint32_t arow = wid * 16 + (lane & 15);
        const uint32_t abyt = (lane >> 4) * 16;
#pragma unroll
        for (int kc = 0; kc < 4; kc++)
            ldsm_x4(qf[kc], sb + KV_STG + arow * LDS_B + kc * 32 + abyt);
    }
    __syncthreads();   // Q frags in regs before tile-1 prefetch reuses buffer

    float accO[8][4];
#pragma unroll
    for (int j = 0; j < 8; j++)
#pragma unroll
        for (int k = 0; k < 4; k++) accO[j][k] = 0.f;
    float m_lo = -1e30f, m_hi = -1e30f, l_lo = 0.f, l_hi = 0.f;

    const int r_lo = q0 + wid * 16 + (lane >> 2);
    const int r_hi = r_lo + 8;
    const uint32_t brow = (lane & 7) + ((lane >> 4) << 3);
    const uint32_t bbyt = ((lane >> 3) & 1) * 16;
    const uint32_t vbyt = (lane >> 4) * 16;

    const int ntiles = 2 * qt + 2;        // >= 2 always

    const int lr = tid >> 3;              // 0..31
    const int lc = (tid & 7) * 16;
    const int le = lc >> 1;

    // prologue: tiles 0 and 1 into stages 0 and 1
#pragma unroll
    for (int pt = 0; pt < 2; pt++) {
        const uint32_t st = sb + pt * KV_STG;
#pragma unroll
        for (int rr = 0; rr < 2; rr++) {
            const int row = lr + rr * 32;
            const uint32_t so = row * LDS_B + lc;
            const size_t go = (size_t)(pt * 64 + row) * DKn + le;
            CP_ASYNC16(st + 0 * KVMAT + so, Kf + go);
            CP_ASYNC16(st + 1 * KVMAT + so, Vf + go);
        }
        CP_COMMIT();
    }

#pragma unroll 1
    for (int kt = 0; kt < ntiles; kt++) {
        CP_WAIT1();
        __syncthreads();

        // prefetch tile kt+2 into (kt+2)%3 (consumed at iter kt-1)
        if (kt + 2 < ntiles) {
            const uint32_t st = sb + ((kt + 2) % 3) * KV_STG;
#pragma unroll
            for (int rr = 0; rr < 2; rr++) {
                const int row = lr + rr * 32;
                const uint32_t so = row * LDS_B + lc;
                const size_t go = (size_t)((kt + 2) * 64 + row) * DKn + le;
                CP_ASYNC16(st + 0 * KVMAT + so, Kf + go);
                CP_ASYNC16(st + 1 * KVMAT + so, Vf + go);
            }
        }
        CP_COMMIT();

        const uint32_t stg = sb + (kt % 3) * KV_STG;
        const int k0 = kt * 64;

        // ---- S = Q K^T, log2-domain scores ----
        float s[8][4];
#pragma unroll
        for (int j = 0; j < 8; j++)
#pragma unroll
            for (int k = 0; k < 4; k++) s[j][k] = 0.f;

#pragma unroll
        for (int kc = 0; kc < 4; kc++) {
#pragma unroll
            for (int nq = 0; nq < 4; nq++) {
                const uint32_t bo = stg + (brow + nq * 16) * LDS_B + kc * 32 + bbyt;
                uint32_t kh[4];
                ldsm_x4(kh, bo);
                mma16816h(s[nq * 2 + 0], qf[kc], kh[0], kh[1]);
                mma16816h(s[nq * 2 + 1], qf[kc], kh[2], kh[3]);
            }
        }

        // ---- causal mask ----
        if ((k0 + 63) > r_lo) {
#pragma unroll
            for (int j = 0; j < 8; j++) {
                const int c = k0 + j * 8 + (lane & 3) * 2;
                if (c > r_lo)     s[j][0] = -1e30f;
                if (c + 1 > r_lo) s[j][1] = -1e30f;
                if (c > r_hi)     s[j][2] = -1e30f;
                if (c + 1 > r_hi) s[j][3] = -1e30f;
            }
        }

        // ---- online softmax (base-2) ----
        float mx0 = -1e30f, mx1 = -1e30f;
#pragma unroll
        for (int j = 0; j < 8; j++) {
            mx0 = fmaxf(mx0, fmaxf(s[j][0], s[j][1]));
            mx1 = fmaxf(mx1, fmaxf(s[j][2], s[j][3]));
        }
        mx0 = fmaxf(mx0, __shfl_xor_sync(0xffffffffu, mx0, 1));
        mx0 = fmaxf(mx0, __shfl_xor_sync(0xffffffffu, mx0, 2));
        mx1 = fmaxf(mx1, __shfl_xor_sync(0xffffffffu, mx1, 1));
        mx1 = fmaxf(mx1, __shfl_xor_sync(0xffffffffu, mx1, 2));
        const float mn0 = fmaxf(m_lo, mx0);
        const float mn1 = fmaxf(m_hi, mx1);
        const float a0 = fexp2(m_lo - mn0);
        const float a1 = fexp2(m_hi - mn1);
        m_lo = mn0; m_hi = mn1;

        float sum0 = 0.f, sum1 = 0.f;
#pragma unroll
        for (int j = 0; j < 8; j++) {
            s[j][0] = fexp2(s[j][0] - mn0);
            s[j][1] = fexp2(s[j][1] - mn0);
            s[j][2] = fexp2(s[j][2] - mn1);
            s[j][3] = fexp2(s[j][3] - mn1);
            sum0 += s[j][0] + s[j][1];
            sum1 += s[j][2] + s[j][3];
        }
        sum0 += __shfl_xor_sync(0xffffffffu, sum0, 1);
        sum0 += __shfl_xor_sync(0xffffffffu, sum0, 2);
        sum1 += __shfl_xor_sync(0xffffffffu, sum1, 1);
        sum1 += __shfl_xor_sync(0xffffffffu, sum1, 2);
        l_lo = l_lo * a0 + sum0;
        l_hi = l_hi * a1 + sum1;
#pragma unroll
        for (int j = 0; j < 8; j++) {
            accO[j][0] *= a0; accO[j][1] *= a0;
            accO[j][2] *= a1; accO[j][3] *= a1;
        }

        // ---- O += P V ----
#pragma unroll
        for (int kc = 0; kc < 4; kc++) {
            uint32_t ph[4];
            ph[0] = packh2(s[2 * kc][0],     s[2 * kc][1]);
            ph[1] = packh2(s[2 * kc][2],     s[2 * kc][3]);
            ph[2] = packh2(s[2 * kc + 1][0], s[2 * kc + 1][1]);
            ph[3] = packh2(s[2 * kc + 1][2], s[2 * kc + 1][3]);
            const uint32_t vrow = kc * 16 + (lane & 15);
#pragma unroll
            for (int np = 0; np < 4; np++) {
                const uint32_t vo = stg + KVMAT + vrow * LDS_B + np * 32 + vbyt;
                uint32_t vh[4];
                ldsm_x4_t(vh, vo);
                mma16816h(accO[np * 2 + 0], ph, vh[0], vh[1]);
                mma16816h(accO[np * 2 + 1], ph, vh[2], vh[3]);
            }
        }
    }

    // ---- epilogue: normalize, write single fp16 [B,S,D] ----
    const float il0 = 1.0f / l_lo;
    const float il1 = 1.0f / l_hi;
    const int b = bh >> 4, h = bh & 15;
    const int c_base = h * DKn + (lane & 3) * 2;
#pragma unroll
    for (int j = 0; j < 8; j++) {
        const int c = c_base + j * 8;
        const size_t i0 = ((size_t)(b * Sn + r_lo)) * Dn + c;
        const size_t i1 = ((size_t)(b * Sn + r_hi)) * Dn + c;
        *(uint32_t*)(g_Af + i0) = packh2(accO[j][0] * il0, accO[j][1] * il0);
        *(uint32_t*)(g_Af + i1) = packh2(accO[j][2] * il1, accO[j][3] * il1);
    }
}

// ---------------------------------------------------------------------------
extern "C" void kernel_launch(void* const* d_in, const int* in_sizes, int n_in,
                              void* d_out, int out_size)
{
    const float* k_in = (const float*)d_in[0];
    const float* q_in = (const float*)d_in[1];
    const float* v_in = (const float*)d_in[2];
    const float* w_q  = (const float*)d_in[3];
    const float* b_q  = (const float*)d_in[4];
    const float* w_k  = (const float*)d_in[5];
    const float* b_k  = (const float*)d_in[6];
    const float* w_v  = (const float*)d_in[7];
    const float* b_v  = (const float*)d_in[8];
    const float* w_o  = (const float*)d_in[9];
    const float* b_o  = (const float*)d_in[10];
    float* out = (float*)d_out;

    __half *xq, *xk, *xv, *wq, *wk, *wv, *wo;
    __half *Qf, *Kf, *Vf, *Af;
    cudaGetSymbolAddress((void**)&xq, g_xq);
    cudaGetSymbolAddress((void**)&xk, g_xk);
    cudaGetSymbolAddress((void**)&xv, g_xv);
    cudaGetSymbolAddress((void**)&wq, g_wq);
    cudaGetSymbolAddress((void**)&wk, g_wk);
    cudaGetSymbolAddress((void**)&wv, g_wv);
    cudaGetSymbolAddress((void**)&wo, g_wo);
    cudaGetSymbolAddress((void**)&Qf, g_Qf);
    cudaGetSymbolAddress((void**)&Kf, g_Kf);
    cudaGetSymbolAddress((void**)&Vf, g_Vf);
    cudaGetSymbolAddress((void**)&Af, g_Af);

    cudaFuncSetAttribute(gemm_proj, cudaFuncAttributeMaxDynamicSharedMemorySize,
                         GEMM_SMEM);
    cudaFuncSetAttribute(gemm_out, cudaFuncAttributeMaxDynamicSharedMemorySize,
                         GEMM_SMEM);
    cudaFuncSetAttribute(attn_tc, cudaFuncAttributeMaxDynamicSharedMemorySize,
                         ATTN_SMEM);

    // one-launch conversion prepass
    conv_all<<<dim3(1024, 7), 256>>>(
        q_in, k_in, v_in, w_q, w_k, w_v, w_o,
        xq, xk, xv, wq, wk, wv, wo);

    // merged Q/K/V projection GEMMs (single fp16; Q pre-scaled into log2 domain)
    GemmJob jq = { xq, wq, b_q, Qf, 0.125f * 1.4426950408889634f };
    GemmJob jk = { xk, wk, b_k, Kf, 1.0f };
    GemmJob jv = { xv, wv, b_v, Vf, 1.0f };
    gemm_proj<<<dim3(32, 8, 3), 256, GEMM_SMEM>>>(jq, jk, jv);

    attn_tc<<<dim3(16, 32), 256, ATTN_SMEM>>>();

    gemm_out<<<dim3(32, 8), 256, GEMM_SMEM>>>(Af, wo, b_o, out);
}